// round 17
// baseline (speedup 1.0000x reference)
#include <cuda_runtime.h>
#include <cuda_fp16.h>

// ============================================================================
// CfC Liquid Neural Network, B=256, T=1024. Round 16 = Round 15 (best) +
//  (1) fp16 z vectors packed [rowA k0..3 | rowB k0..3] per 16B slot — one
//      LDS.128 serves both rows per k4 (dot LSU 4 -> 3 ops/iter),
//  (2) cell2+epi2 under named bar.sync(384); final step barrier removed
//      (private act2 buffer) so epi2 tail overlaps next step's cell0.
//  - fp16 weights (fp32 acc) packed half2 (k,k+1) [k2][u]; FFMA2.
//  - 128 CTAs x 512 threads, 2 batch rows per CTA, 1024-step recurrence.
//  - cell1+cell2 weights smem-resident; cell0 streamed from L2 (KS0=5,
//    software-pipelined prefetch). Fast MUFU activations. fc head hoisted.
// ============================================================================

#define F0 128
#define U0 135
#define C0 263
#define CP0 264
#define UP0 136
#define F1 135
#define U1 89
#define C1 224
#define CP1 224
#define UP1 92
#define F2 89
#define U2 32
#define C2 121
#define CP2 128
#define UP2 32

#define L0_MAT (CP0*UP0)            // 35904 halves per mat
#define L1_MAT (CP1*UP1)            // 20608
#define L2_MAT (CP2*UP2)            // 4096
#define OFF_W0 0
#define OFF_W1 (3*L0_MAT)
#define OFF_W2 (OFF_W1 + 3*L1_MAT)
#define TOT_W  (OFF_W2 + 3*L2_MAT)

#define OFF_B0 0
#define OFF_B1 (3*UP0)
#define OFF_B2 (OFF_B1 + 3*UP1)
#define TOT_B  (OFF_B2 + 3*UP2)

__device__ __align__(16) __half g_wh[TOT_W];
__device__ float g_b[TOT_B];

// ---- packed fp32x2 FMA: d = a*b + d (one SASS FFMA2 issue) ----
__device__ __forceinline__ void fma2(float2& d, const float2& a, const float2& b)
{
    unsigned long long& dv = reinterpret_cast<unsigned long long&>(d);
    asm("fma.rn.f32x2 %0, %1, %2, %0;"
        : "+l"(dv)
        : "l"(reinterpret_cast<const unsigned long long&>(a)),
          "l"(reinterpret_cast<const unsigned long long&>(b)));
}

// ---- fast activations (MUFU-based; saturate correctly at +-inf) ----
__device__ __forceinline__ float fast_tanh(float x)
{
    float e = __expf(2.f * x);
    return 1.f - __fdividef(2.f, e + 1.f);
}
__device__ __forceinline__ float fast_sigmoid(float x)
{
    return __fdividef(1.f, 1.f + __expf(-x));
}

// ---- Pack: half linear idx within mat = (k2*UP + u)*2 + r, k = 2*k2 + r ----
template<int C, int CP, int U, int UP>
__global__ void pack_kernel(int woff, int boff,
    const float* __restrict__ ff1w, const float* __restrict__ ff1b,
    const float* __restrict__ ff2w, const float* __restrict__ ff2b,
    const float* __restrict__ taw,  const float* __restrict__ tab,
    const float* __restrict__ tbw,  const float* __restrict__ tbb,
    const int*   __restrict__ mask)
{
    const int per = CP * UP;
    const int n = 3 * per;
    for (int idx = blockIdx.x * blockDim.x + threadIdx.x; idx < n;
         idx += gridDim.x * blockDim.x) {
        int mat = idx / per;
        int e = idx - mat * per;
        int r = e & 1;
        int t1 = e >> 1;
        int u = t1 % UP;
        int k2 = t1 / UP;
        int c = 2 * k2 + r;
        float v = 0.f;
        if (c < C && u < U) {
            int src = u * C + c;
            if (mat == 0)      v = ff1w[src] * (float)mask[src];
            else if (mat == 1) v = ff2w[src] * (float)mask[src];
            else               v = taw[src] + tbw[src];
        }
        g_wh[woff + idx] = __float2half_rn(v);
    }
    for (int idx = blockIdx.x * blockDim.x + threadIdx.x; idx < 3 * UP;
         idx += gridDim.x * blockDim.x) {
        int mat = idx / UP;
        int u = idx - mat * UP;
        float v = 0.f;
        if (u < U) v = (mat == 0) ? ff1b[u] : (mat == 1 ? ff2b[u] : (tab[u] + tbb[u]));
        g_b[boff + idx] = v;
    }
}

// ---- FMA block: weights wa(k01),wc(k23) for 4 units; z slot zz = both rows ----
__device__ __forceinline__ void fma_blk(
    const uint4& wa, const uint4& wc, const uint4& zz, float2 acc[8])
{
    float2 A01 = __half22float2(*(const __half2*)&zz.x);   // row A, k0,k1
    float2 A23 = __half22float2(*(const __half2*)&zz.y);   // row A, k2,k3
    float2 B01 = __half22float2(*(const __half2*)&zz.z);   // row B, k0,k1
    float2 B23 = __half22float2(*(const __half2*)&zz.w);   // row B, k2,k3
    float2 w;
    w = __half22float2(*(const __half2*)&wa.x);
    fma2(acc[0], w, A01); fma2(acc[1], w, B01);
    w = __half22float2(*(const __half2*)&wa.y);
    fma2(acc[2], w, A01); fma2(acc[3], w, B01);
    w = __half22float2(*(const __half2*)&wa.z);
    fma2(acc[4], w, A01); fma2(acc[5], w, B01);
    w = __half22float2(*(const __half2*)&wa.w);
    fma2(acc[6], w, A01); fma2(acc[7], w, B01);
    w = __half22float2(*(const __half2*)&wc.x);
    fma2(acc[0], w, A23); fma2(acc[1], w, B23);
    w = __half22float2(*(const __half2*)&wc.y);
    fma2(acc[2], w, A23); fma2(acc[3], w, B23);
    w = __half22float2(*(const __half2*)&wc.z);
    fma2(acc[4], w, A23); fma2(acc[5], w, B23);
    w = __half22float2(*(const __half2*)&wc.w);
    fma2(acc[6], w, A23); fma2(acc[7], w, B23);
}

// ---- Dot task (smem weights): plain loop ----
template<int UP>
__device__ __forceinline__ void dot2(
    const uint4* __restrict__ wbase, const uint4* __restrict__ zh,
    int ub, int kb, int ke, float2 acc[8])
{
    const uint4* wp = wbase + (size_t)(2 * kb) * (UP / 4) + ub;
#pragma unroll 4
    for (int k4 = kb; k4 < ke; ++k4) {
        uint4 wa = wp[0];
        uint4 wc = wp[UP / 4];
        wp += UP / 2;
        fma_blk(wa, wc, zh[k4], acc);
    }
}

// ---- Dot task (L2-streamed weights): software-pipelined prefetch ----
template<int UP>
__device__ __forceinline__ void dot2g(
    const uint4* __restrict__ wbase, const uint4* __restrict__ zh,
    int ub, int kb, int ke, float2 acc[8])
{
    const uint4* wp = wbase + (size_t)(2 * kb) * (UP / 4) + ub;
    uint4 wa = wp[0];
    uint4 wc = wp[UP / 4];
#pragma unroll 4
    for (int k4 = kb; k4 < ke - 1; ++k4) {
        wp += UP / 2;
        uint4 na = wp[0];          // issued BEFORE the FMA block: overlap
        uint4 nc = wp[UP / 4];
        fma_blk(wa, wc, zh[k4], acc);
        wa = na; wc = nc;
    }
    fma_blk(wa, wc, zh[ke - 1], acc);
}

// ---- smem layout (byte offsets; all multiples of 16) ----
// z buffers: one uint4 per k4 group = 8 halves [rowA k0..3 | rowB k0..3]
#define SB_W1   0                            // 123648
#define SB_W2   (SB_W1 + 3*L1_MAT*2)         // 123648 (+24576)
#define SB_B    (SB_W2 + 3*L2_MAT*2)         // 148224 (+3120)
#define SB_Z0   (SB_B + TOT_B*4)             // 151344 (+66*16 = 1056)
#define SB_Z1   (SB_Z0 + 66*16)              // 152400 (+896)
#define SB_Z2   (SB_Z1 + 56*16)              // 153296 (+512)
#define SB_A0   (SB_Z2 + 32*16)              // 153808 (+16320)
#define SB_A1   (SB_A0 + 3*5*2*UP0*4)        // 170128 (+15456)
#define SB_A2   (SB_A1 + 3*7*2*UP1*4)        // 185584 (+12288)
#define SB_TOT  (SB_A2 + 3*16*2*UP2*4)       // 197872 B

#define KS0 5
#define KS1 7
#define KS2 16

__global__ __launch_bounds__(512, 1)
void lnn_main(const float* __restrict__ x, float* __restrict__ out)
{
    extern __shared__ __align__(16) char smraw[];
    float*  sb  = (float*)(smraw + SB_B);
    __half* z0h = (__half*)(smraw + SB_Z0);   // idx = k4*8 + row*4 + (col&3)
    __half* z1h = (__half*)(smraw + SB_Z1);
    __half* z2h = (__half*)(smraw + SB_Z2);
    float*  act0 = (float*)(smraw + SB_A0);
    float*  act1 = (float*)(smraw + SB_A1);
    float*  act2 = (float*)(smraw + SB_A2);
    const uint4* sW1v = (const uint4*)(smraw + SB_W1);
    const uint4* sW2v = (const uint4*)(smraw + SB_W2);
    const uint4* gw0  = (const uint4*)g_wh;      // OFF_W0 == 0
    const uint4* z0v = (const uint4*)z0h;
    const uint4* z1v = (const uint4*)z1h;
    const uint4* z2v = (const uint4*)z2h;

    const int tid = threadIdx.x;

    // Fill smem caches
    {
        const uint4* gsrc = (const uint4*)g_wh;
        uint4* d1 = (uint4*)(smraw + SB_W1);
        uint4* d2 = (uint4*)(smraw + SB_W2);
        for (int i = tid; i < 3 * L1_MAT / 8; i += 512) d1[i] = gsrc[OFF_W1 / 8 + i];
        for (int i = tid; i < 3 * L2_MAT / 8; i += 512) d2[i] = gsrc[OFF_W2 / 8 + i];
    }
    for (int i = tid; i < TOT_B; i += 512) sb[i] = g_b[i];
    {
        uint4* zz = (uint4*)(smraw + SB_Z0);   // z0,z1,z2 contiguous: 154 uint4
        for (int i = tid; i < 154; i += 512) zz[i] = make_uint4(0, 0, 0, 0);
    }
    __syncthreads();

    const int b0 = blockIdx.x * 2;
    const float4* xv = (const float4*)x + (size_t)b0 * 1024 * 32;
    // x-prefetch threads: 448..511 (disjoint from epi0's 0..269)
    const int xr = (tid - 448) >> 5, xi = (tid - 448) & 31;

    float4 xreg = make_float4(0.f, 0.f, 0.f, 0.f);
    if (tid >= 448) {
        float4 v = xv[((size_t)xr * 1024 + 0) * 32 + xi];
        __half2 p0 = __floats2half2_rn(v.x, v.y);
        __half2 p1 = __floats2half2_rn(v.z, v.w);
        *(__half2*)&z0h[xi * 8 + xr * 4 + 0] = p0;
        *(__half2*)&z0h[xi * 8 + xr * 4 + 2] = p1;
    }
    __syncthreads();
    if (tid >= 448) xreg = xv[((size_t)xr * 1024 + 1) * 32 + xi];

    for (int t = 0; t < 1024; ++t) {
        // ======== Cell 0 (L2-streamed, pipelined): 3 x 34 x 5 = 510 tasks
        if (tid < 510) {
            int ub = tid % 34, q = tid / 34;
            int ks = q % KS0, mat = q / KS0;
            int u0 = 4 * ub;
            float2 acc[8];
#pragma unroll
            for (int u = 0; u < 4; ++u) {
                float bv = (ks == 0) ? sb[OFF_B0 + mat * UP0 + u0 + u] : 0.f;
                acc[2 * u]     = make_float2(bv, 0.f);
                acc[2 * u + 1] = make_float2(bv, 0.f);
            }
            int kb = (ks * 66) / KS0, ke = ((ks + 1) * 66) / KS0;
            dot2g<UP0>(gw0 + mat * (L0_MAT / 8), z0v, ub, kb, ke, acc);
            float* ap = act0 + ((mat * KS0 + ks) * 2) * UP0 + u0;
            *(float4*)ap         = make_float4(acc[0].x + acc[0].y, acc[2].x + acc[2].y,
                                               acc[4].x + acc[4].y, acc[6].x + acc[6].y);
            *(float4*)(ap + UP0) = make_float4(acc[1].x + acc[1].y, acc[3].x + acc[3].y,
                                               acc[5].x + acc[5].y, acc[7].x + acc[7].y);
        }
        __syncthreads();

        // ======== epi0 (270 thr) fused with x_{t+1} store (threads 448+)
        if (tid < 270) {
            int u = tid >> 1, r = tid & 1;
            float f1 = 0.f, f2 = 0.f, tt = 0.f;
#pragma unroll
            for (int ks = 0; ks < KS0; ++ks) {
                f1 += act0[((0 * KS0 + ks) * 2 + r) * UP0 + u];
                f2 += act0[((1 * KS0 + ks) * 2 + r) * UP0 + u];
                tt += act0[((2 * KS0 + ks) * 2 + r) * UP0 + u];
            }
            f1 = fast_tanh(f1); f2 = fast_tanh(f2);
            float s = fast_sigmoid(tt);
            float h = f1 + s * (f2 - f1);
            __half hh = __float2half_rn(h);
            int c0 = 128 + u;                       // z0 self-recurrence
            z0h[(c0 >> 2) * 8 + r * 4 + (c0 & 3)] = hh;
            z1h[(u >> 2) * 8 + r * 4 + (u & 3)]   = hh;   // cell1 input
        } else if (tid >= 448) {
            __half2 p0 = __floats2half2_rn(xreg.x, xreg.y);
            __half2 p1 = __floats2half2_rn(xreg.z, xreg.w);
            *(__half2*)&z0h[xi * 8 + xr * 4 + 0] = p0;    // x_{t+1} (x-slice dead)
            *(__half2*)&z0h[xi * 8 + xr * 4 + 2] = p1;
        }
        __syncthreads();
        if (tid >= 448) {
            int tn = (t + 2 < 1024) ? t + 2 : 1023;
            xreg = xv[((size_t)xr * 1024 + tn) * 32 + xi];
        }

        // ======== Cell 1 (smem fp16): 3 mats x 23 ublk x 7 ks = 483 tasks
        if (tid < 483) {
            int ub = tid % 23, q = tid / 23;
            int ks = q % KS1, mat = q / KS1;
            int u0 = 4 * ub;
            float2 acc[8];
#pragma unroll
            for (int u = 0; u < 4; ++u) {
                float bv = (ks == 0) ? sb[OFF_B1 + mat * UP1 + u0 + u] : 0.f;
                acc[2 * u]     = make_float2(bv, 0.f);
                acc[2 * u + 1] = make_float2(bv, 0.f);
            }
            int kb = ks * 8, ke = kb + 8;
            dot2<UP1>(sW1v + mat * (L1_MAT / 8), z1v, ub, kb, ke, acc);
            float* ap = act1 + ((mat * KS1 + ks) * 2) * UP1 + u0;
            *(float4*)ap         = make_float4(acc[0].x + acc[0].y, acc[2].x + acc[2].y,
                                               acc[4].x + acc[4].y, acc[6].x + acc[6].y);
            *(float4*)(ap + UP1) = make_float4(acc[1].x + acc[1].y, acc[3].x + acc[3].y,
                                               acc[5].x + acc[5].y, acc[7].x + acc[7].y);
        }
        __syncthreads();
        if (tid < 178) {
            int u = tid >> 1, r = tid & 1;
            float f1 = 0.f, f2 = 0.f, tt = 0.f;
#pragma unroll
            for (int ks = 0; ks < KS1; ++ks) {
                f1 += act1[((0 * KS1 + ks) * 2 + r) * UP1 + u];
                f2 += act1[((1 * KS1 + ks) * 2 + r) * UP1 + u];
                tt += act1[((2 * KS1 + ks) * 2 + r) * UP1 + u];
            }
            f1 = fast_tanh(f1); f2 = fast_tanh(f2);
            float s = fast_sigmoid(tt);
            float h = f1 + s * (f2 - f1);
            __half hh = __float2half_rn(h);
            int c0 = 135 + u;                       // z1 self-recurrence
            z1h[(c0 >> 2) * 8 + r * 4 + (c0 & 3)] = hh;
            z2h[(u >> 2) * 8 + r * 4 + (u & 3)]   = hh;   // cell2 input
        }
        __syncthreads();

        // ======== Cell 2 + epi2: warps 0..11 only; named barrier; the step's
        //          final barrier is REMOVED so warps 12..15 (and finished
        //          warps) flow straight into next step's cell0.
        if (tid < 384) {
            int ub = tid & 7, q = tid >> 3;
            int ks = q & 15, mat = q >> 4;
            int u0 = 4 * ub;
            float2 acc[8];
#pragma unroll
            for (int u = 0; u < 4; ++u) {
                float bv = (ks == 0) ? sb[OFF_B2 + mat * UP2 + u0 + u] : 0.f;
                acc[2 * u]     = make_float2(bv, 0.f);
                acc[2 * u + 1] = make_float2(bv, 0.f);
            }
            int kb = ks * 2, ke = kb + 2;
            dot2<UP2>(sW2v + mat * (L2_MAT / 8), z2v, ub, kb, ke, acc);
            float* ap = act2 + ((mat * KS2 + ks) * 2) * UP2 + u0;
            *(float4*)ap         = make_float4(acc[0].x + acc[0].y, acc[2].x + acc[2].y,
                                               acc[4].x + acc[4].y, acc[6].x + acc[6].y);
            *(float4*)(ap + UP2) = make_float4(acc[1].x + acc[1].y, acc[3].x + acc[3].y,
                                               acc[5].x + acc[5].y, acc[7].x + acc[7].y);
            asm volatile("bar.sync 4, 384;" ::: "memory");
            if (tid < 64) {
                int u = tid >> 1, r = tid & 1;
                float f1 = 0.f, f2 = 0.f, tt = 0.f;
#pragma unroll
                for (int ks = 0; ks < KS2; ++ks) {
                    f1 += act2[((0 * KS2 + ks) * 2 + r) * UP2 + u];
                    f2 += act2[((1 * KS2 + ks) * 2 + r) * UP2 + u];
                    tt += act2[((2 * KS2 + ks) * 2 + r) * UP2 + u];
                }
                f1 = fast_tanh(f1); f2 = fast_tanh(f2);
                float s = fast_sigmoid(tt);
                float h = f1 + s * (f2 - f1);
                int c0 = 89 + u;                    // z2 self-recurrence
                z2h[(c0 >> 2) * 8 + r * 4 + (c0 & 3)] = __float2half_rn(h);
                out[(((size_t)(b0 + r)) * 1024 + t) * 32 + u] = h;
            }
        }
        // no final __syncthreads: next step's cell0 (reads z0h, writes act0)
        // is hazard-free vs epi2 (reads act2, writes z2h/out); z0h's h0/x
        // slices are protected by the barriers after epi0.
    }
}

// ---- fc head applied in place over out[256*1024][32] ----
__global__ __launch_bounds__(256)
void fc_kernel(float* __restrict__ out, const float* __restrict__ fcw,
               const float* __restrict__ fcb)
{
    __shared__ float w[1024];
    __shared__ float b[32];
    int tid = threadIdx.x;
    for (int i = tid; i < 1024; i += 256) w[i] = fcw[i];
    if (tid < 32) b[tid] = fcb[tid];
    __syncthreads();

    size_t pos = (size_t)blockIdx.x * 256 + tid;
    float4* p = reinterpret_cast<float4*>(out) + pos * 8;
    float h[32];
    float4 v[8];
#pragma unroll
    for (int i = 0; i < 8; ++i) v[i] = p[i];
#pragma unroll
    for (int i = 0; i < 8; ++i) {
        h[4 * i + 0] = v[i].x; h[4 * i + 1] = v[i].y;
        h[4 * i + 2] = v[i].z; h[4 * i + 3] = v[i].w;
    }
#pragma unroll
    for (int i = 0; i < 8; ++i) {
        float y[4];
#pragma unroll
        for (int j = 0; j < 4; ++j) {
            int o = 4 * i + j;
            float acc = b[o];
#pragma unroll
            for (int u = 0; u < 32; ++u) acc = fmaf(w[o * 32 + u], h[u], acc);
            y[j] = acc;
        }
        p[i] = make_float4(y[0], y[1], y[2], y[3]);
    }
}

// ============================================================================
extern "C" void kernel_launch(void* const* d_in, const int* in_sizes, int n_in,
                              void* d_out, int out_size)
{
    (void)n_in; (void)out_size;
    int base[3], mi[3], fwi, fbi;
    if (in_sizes[9] == U0 * C0) {          // interleaved dict order
        base[0] = 1;  mi[0] = 9;
        base[1] = 10; mi[1] = 18;
        base[2] = 19; mi[2] = 27;
        fwi = 28; fbi = 29;
    } else {                                // signature order
        base[0] = 1; base[1] = 9; base[2] = 17;
        fwi = 25; fbi = 26;
        mi[0] = 27; mi[1] = 28; mi[2] = 29;
    }

    const float* xin = (const float*)d_in[0];
    const float* fcw = (const float*)d_in[fwi];
    const float* fcb = (const float*)d_in[fbi];

#define LPTRS(l) \
    (const float*)d_in[base[l]+0], (const float*)d_in[base[l]+1], \
    (const float*)d_in[base[l]+2], (const float*)d_in[base[l]+3], \
    (const float*)d_in[base[l]+4], (const float*)d_in[base[l]+5], \
    (const float*)d_in[base[l]+6], (const float*)d_in[base[l]+7], \
    (const int*)d_in[mi[l]]

    pack_kernel<C0, CP0, U0, UP0><<<(3 * L0_MAT + 255) / 256, 256>>>(OFF_W0, OFF_B0, LPTRS(0));
    pack_kernel<C1, CP1, U1, UP1><<<(3 * L1_MAT + 255) / 256, 256>>>(OFF_W1, OFF_B1, LPTRS(1));
    pack_kernel<C2, CP2, U2, UP2><<<(3 * L2_MAT + 255) / 256, 256>>>(OFF_W2, OFF_B2, LPTRS(2));
#undef LPTRS

    static_assert(SB_TOT <= 232448, "smem over budget");
    cudaFuncSetAttribute(lnn_main, cudaFuncAttributeMaxDynamicSharedMemorySize,
                         SB_TOT);
    lnn_main<<<128, 512, SB_TOT>>>(xin, (float*)d_out);
    fc_kernel<<<1024, 256>>>((float*)d_out, fcw, fcb);
}